// round 13
// baseline (speedup 1.0000x reference)
#include <cuda_runtime.h>
#include <math.h>
#include <stdint.h>

#define OBS_DIM 256
#define ACT_DIM 64
#define T_TOT   22
#define HID     32
#define MAXW    15
#define NSTEP   15
#define NGATE   96
#define KDIM    320
#define MAXB    8192
#define NCHUNK  2

// GRU pre-activation scratch: GI[(b*15+t)*96 + g]
__device__ float g_GI[(size_t)MAXB * NSTEP * NGATE];
// W_ih fragment-packed: [kt(10)][ks(4)][bn(96)][brow(4)] float4{bh0,bh1,bl0,bl1}
__device__ __align__(16) float4 g_Wp[10 * 4 * NGATE * 4];

__device__ __forceinline__ uint32_t tf32hi_bits(float x) {
    uint32_t h;
    asm("cvt.rna.tf32.f32 %0, %1;" : "=r"(h) : "f"(x));
    return h;
}

__device__ __forceinline__ void mma_tf32(float* c, uint32_t a0, uint32_t a1,
                                         uint32_t a2, uint32_t a3,
                                         uint32_t b0, uint32_t b1) {
    asm volatile(
        "mma.sync.aligned.m16n8k8.row.col.f32.tf32.tf32.f32 "
        "{%0,%1,%2,%3}, {%4,%5,%6,%7}, {%8,%9}, {%0,%1,%2,%3};\n"
        : "+f"(c[0]), "+f"(c[1]), "+f"(c[2]), "+f"(c[3])
        : "r"(a0), "r"(a1), "r"(a2), "r"(a3), "r"(b0), "r"(b1));
}

// ---------- cp.async ----------
__device__ __forceinline__ void cp16(uint32_t dst, const void* src) {
    asm volatile("cp.async.ca.shared.global [%0], [%1], 16;"
                 :: "r"(dst), "l"(src) : "memory");
}
__device__ __forceinline__ void cp_commit() {
    asm volatile("cp.async.commit_group;" ::: "memory");
}
template <int N>
__device__ __forceinline__ void cp_wait() {
    asm volatile("cp.async.wait_group %0;" :: "n"(N) : "memory");
}

__device__ __forceinline__ float wsum(float x) {
#pragma unroll
    for (int o = 16; o; o >>= 1) x += __shfl_xor_sync(0xffffffffu, x, o);
    return x;
}
__device__ __forceinline__ float wmax(float x) {
#pragma unroll
    for (int o = 16; o; o >>= 1) x = fmaxf(x, __shfl_xor_sync(0xffffffffu, x, o));
    return x;
}
__device__ __forceinline__ float sigm(float x) { return 1.f / (1.f + __expf(-x)); }
__device__ __forceinline__ float tanh_fast(float x) {
    float e = __expf(-2.f * fabsf(x));
    float r = (1.f - e) / (1.f + e);
    return copysignf(r, x);
}

// =====================================================================
// Kernel 0: pack W_ih into fragment-ready tf32 hi/lo quads.
// =====================================================================
__global__ void k_wprep(const float* __restrict__ Wih) {
    int p = blockIdx.x * 256 + threadIdx.x;
    if (p >= 10 * 4 * NGATE * 4) return;
    int brow = p & 3;
    int t = p >> 2;
    int bn = t % NGATE;
    int kk8 = t / NGATE;              // 0..39
    int k = kk8 * 8 + brow;
    float x0 = Wih[(size_t)bn * KDIM + k];
    float x1 = Wih[(size_t)bn * KDIM + k + 4];
    float h0 = __uint_as_float(tf32hi_bits(x0));
    float h1 = __uint_as_float(tf32hi_bits(x1));
    g_Wp[p] = make_float4(h0, h1, x0 - h0, x1 - h1);
}

// =====================================================================
// Kernel 1: tensor-core GEMM, cp.async double-buffered, batch-chunked.
// GI rows [b0*15, (b0+Bc)*15) = X @ W^T + b
// CTA: 128 thr, tile 128m x 96n, warp tile 32m x 96n.
// =====================================================================
#define XSTR 36
#define XTILE (128 * XSTR)                 // floats per X buffer (4608)
#define WTILE (4 * NGATE * 4)              // float4s per W k-tile (1536)
#define GEMM_SMEM_BYTES (2 * XTILE * 4 + 2 * WTILE * 16)   // 86016

__global__ __launch_bounds__(128) void k_gemm_mma(
    const float* __restrict__ obs, const float* __restrict__ act,
    const float* __restrict__ bih, int b0, int Bc)
{
    extern __shared__ __align__(16) float4 smem4[];
    float*  Xs = (float*)smem4;                     // [2][128][XSTR] fp32
    float4* Wp = smem4 + (2 * XTILE) / 4;           // [2][4][96][4]
    __shared__ float sbias[96];

    const int tid = threadIdx.x;
    const int warp = tid >> 5, lane = tid & 31;
    const int Mtot = Bc * NSTEP;                    // rows in this chunk
    const int m_base = blockIdx.x * 128;

    if (tid < 96) sbias[tid] = bih[tid];

    // per-thread X-load row indices (8 rows, fixed across k-tiles)
    int rowptr[8];
#pragma unroll
    for (int i = 0; i < 8; i++) {
        int idx = i * 128 + tid;
        int r = idx >> 3;
        int gm = m_base + r;
        int gmc = gm < Mtot ? gm : Mtot - 1;
        int bb = b0 + gmc / NSTEP;
        int tt = gmc % NSTEP;
        rowptr[i] = bb * T_TOT + tt;
    }
    const int c4 = tid & 7;

    const uint32_t xs_addr = (uint32_t)__cvta_generic_to_shared(Xs);
    const uint32_t wp_addr = (uint32_t)__cvta_generic_to_shared(Wp);

    auto load_tile = [&](int pb, int kt) {
        const int k0 = kt * 32;
        const uint32_t xb = xs_addr + (uint32_t)pb * XTILE * 4;
#pragma unroll
        for (int i = 0; i < 8; i++) {
            int idx = i * 128 + tid;
            int r = idx >> 3;
            int kk = k0 + c4 * 4;
            const float* src = (k0 < OBS_DIM)
                ? obs + (size_t)rowptr[i] * OBS_DIM + kk
                : act + (size_t)rowptr[i] * ACT_DIM + (kk - OBS_DIM);
            cp16(xb + (uint32_t)(r * XSTR + c4 * 4) * 4, src);
        }
        const uint32_t wb = wp_addr + (uint32_t)pb * WTILE * 16;
        const float4* gW = g_Wp + (size_t)kt * WTILE;
#pragma unroll
        for (int i = 0; i < 12; i++) {
            int idx = i * 128 + tid;
            cp16(wb + (uint32_t)idx * 16, gW + idx);
        }
    };

    float acc[2][12][4];
#pragma unroll
    for (int mt = 0; mt < 2; mt++)
#pragma unroll
        for (int nt = 0; nt < 12; nt++)
#pragma unroll
            for (int q = 0; q < 4; q++) acc[mt][nt][q] = 0.f;

    const int ar = lane >> 2, ac = lane & 3;
    const int brow = lane & 3, bcol = lane >> 2;
    const int m0 = warp * 32;

    load_tile(0, 0);
    cp_commit();

#pragma unroll 1
    for (int kt = 0; kt < 10; kt++) {
        const int pb = kt & 1;
        if (kt + 1 < 10) {
            load_tile((kt + 1) & 1, kt + 1);
            cp_commit();
            cp_wait<1>();
        } else {
            cp_wait<0>();
        }
        __syncthreads();

        const float* xp = Xs + pb * XTILE;
        const float4* wp = Wp + pb * WTILE;

#pragma unroll
        for (int ks = 0; ks < 4; ks++) {
            const int kk = ks * 8;
            uint32_t ah[2][4], al[2][4];
#pragma unroll
            for (int mt = 0; mt < 2; mt++) {
                int mr = m0 + mt * 16 + ar;
                float x0 = xp[mr * XSTR + kk + ac];
                float x1 = xp[(mr + 8) * XSTR + kk + ac];
                float x2 = xp[mr * XSTR + kk + ac + 4];
                float x3 = xp[(mr + 8) * XSTR + kk + ac + 4];
                uint32_t h0 = tf32hi_bits(x0);
                uint32_t h1 = tf32hi_bits(x1);
                uint32_t h2 = tf32hi_bits(x2);
                uint32_t h3 = tf32hi_bits(x3);
                ah[mt][0] = h0; al[mt][0] = __float_as_uint(x0 - __uint_as_float(h0));
                ah[mt][1] = h1; al[mt][1] = __float_as_uint(x1 - __uint_as_float(h1));
                ah[mt][2] = h2; al[mt][2] = __float_as_uint(x2 - __uint_as_float(h2));
                ah[mt][3] = h3; al[mt][3] = __float_as_uint(x3 - __uint_as_float(h3));
            }
            const float4* wrow = wp + ks * (NGATE * 4);
#pragma unroll
            for (int nt = 0; nt < 12; nt++) {
                float4 bf = wrow[(nt * 8 + bcol) * 4 + brow];
                uint32_t bh0 = __float_as_uint(bf.x);
                uint32_t bh1 = __float_as_uint(bf.y);
                uint32_t bl0 = __float_as_uint(bf.z);
                uint32_t bl1 = __float_as_uint(bf.w);
#pragma unroll
                for (int mt = 0; mt < 2; mt++) {
                    mma_tf32(acc[mt][nt], ah[mt][0], ah[mt][1], ah[mt][2], ah[mt][3], bh0, bh1);
                    mma_tf32(acc[mt][nt], ah[mt][0], ah[mt][1], ah[mt][2], ah[mt][3], bl0, bl1);
                    mma_tf32(acc[mt][nt], al[mt][0], al[mt][1], al[mt][2], al[mt][3], bh0, bh1);
                }
            }
        }
        __syncthreads();
    }

    // ---- epilogue: C fragments -> GI with bias ----
    const size_t grow0 = (size_t)b0 * NSTEP;
#pragma unroll
    for (int mt = 0; mt < 2; mt++) {
        const int r0 = m_base + m0 + mt * 16 + (lane >> 2);
        const int r1 = r0 + 8;
#pragma unroll
        for (int nt = 0; nt < 12; nt++) {
            int cc = nt * 8 + 2 * (lane & 3);
            float bx = sbias[cc], by = sbias[cc + 1];
            if (r0 < Mtot) {
                float2 o = make_float2(acc[mt][nt][0] + bx, acc[mt][nt][1] + by);
                *(float2*)(g_GI + (grow0 + r0) * NGATE + cc) = o;
            }
            if (r1 < Mtot) {
                float2 o = make_float2(acc[mt][nt][2] + bx, acc[mt][nt][3] + by);
                *(float2*)(g_GI + (grow0 + r1) * NGATE + cc) = o;
            }
        }
    }
}

// =====================================================================
// Kernel 2 (fused, R9 known-good 96.5us), batch-chunked [b0, b0+Bc)
// =====================================================================
__global__ __launch_bounds__(256, 3) void k_fused(
    const float* __restrict__ obs, const float* __restrict__ act,
    const float* __restrict__ Whh, const float* __restrict__ bhh,
    const float* __restrict__ lng, const float* __restrict__ lnb,
    const float* __restrict__ W1, const float* __restrict__ b1,
    const float* __restrict__ W2, const float* __restrict__ b2,
    const float* __restrict__ W3, const float* __restrict__ b3,
    float* __restrict__ out, int b0, int Bc, int Bn)
{
    __shared__ float whr[32][33], whz[32][33], whn[32][33];
    __shared__ float w1s[64 * 35];
    __shared__ float w2s[32 * 65];
    __shared__ float w3s[14 * 33];
    __shared__ float b1s[64], b2s[32], b3s[14];
    __shared__ float gms[35], bts[35];
    __shared__ float wbuf[8][144];
    __shared__ float hs[8][32];

    const int tid = threadIdx.x;
    for (int i = tid; i < 3 * HID * HID; i += 256) {
        int row = i >> 5, k = i & 31;
        float v = Whh[i];
        if (row < 32)       whr[row][k] = v;
        else if (row < 64)  whz[row - 32][k] = v;
        else                whn[row - 64][k] = v;
    }
    for (int i = tid; i < 64 * 35; i += 256) w1s[i] = W1[i];
    for (int i = tid; i < 32 * 64; i += 256) w2s[(i >> 6) * 65 + (i & 63)] = W2[i];
    for (int i = tid; i < 14 * 32; i += 256) w3s[(i >> 5) * 33 + (i & 31)] = W3[i];
    if (tid < 64) b1s[tid] = b1[tid];
    if (tid < 32) b2s[tid] = b2[tid];
    if (tid < 14) b3s[tid] = b3[tid];
    if (tid < 35) { gms[tid] = lng[tid]; bts[tid] = lnb[tid]; }
    __syncthreads();

    const int warp = tid >> 5, j = tid & 31;
    const int b = b0 + blockIdx.x * 8 + warp;
    if (b >= b0 + Bc) return;

    // ================= features FIRST ===================================
    float entropy, roc, corr;
    {
        const float* op = obs + (size_t)b * T_TOT * OBS_DIM;
        float o11[8], o12[8], o13[8], o14[8];
#pragma unroll
        for (int i = 0; i < 8; i++) {
            o11[i] = op[11 * OBS_DIM + i * 32 + j];
            o12[i] = op[12 * OBS_DIM + i * 32 + j];
            o13[i] = op[13 * OBS_DIM + i * 32 + j];
            o14[i] = op[14 * OBS_DIM + i * 32 + j];
        }

        float mx = o14[0];
#pragma unroll
        for (int i = 1; i < 8; i++) mx = fmaxf(mx, o14[i]);
        mx = wmax(mx);
        float s = 0.f;
#pragma unroll
        for (int i = 0; i < 8; i++) s += __expf(o14[i] - mx);
        s = wsum(s);
        float inv_s = 1.f / s;
        float es = 0.f;
#pragma unroll
        for (int i = 0; i < 8; i++) {
            float p = __expf(o14[i] - mx) * inv_s;
            es += p * __logf(p + 1e-8f);
        }
        es = wsum(es);
        entropy = -es;

        float d2a = 0.f, d2b = 0.f, d2c = 0.f;
#pragma unroll
        for (int i = 0; i < 8; i++) {
            float da = o12[i] - o11[i]; d2a = fmaf(da, da, d2a);
            float db = o13[i] - o12[i]; d2b = fmaf(db, db, d2b);
            float dc = o14[i] - o13[i]; d2c = fmaf(dc, dc, d2c);
        }
        d2a = wsum(d2a); d2b = wsum(d2b); d2c = wsum(d2c);
        roc = (sqrtf(d2a) + sqrtf(d2b) + sqrtf(d2c)) * (1.f / 3.f);

        float osum = 0.f;
#pragma unroll
        for (int i = 0; i < 8; i++) osum += o14[i];
        osum = wsum(osum);
        float om = osum * (1.f / 256.f);
        const float* ap = act + ((size_t)b * T_TOT + 13) * ACT_DIM;
        float a0 = ap[j], a1 = ap[32 + j];
        float am = wsum(a0 + a1) * (1.f / 256.f);
        float num = 0.f, do2 = 0.f;
#pragma unroll
        for (int i = 0; i < 8; i++) {
            float oc = o14[i] - om;
            do2 = fmaf(oc, oc, do2);
            float acv = ((i == 0) ? a0 : (i == 1) ? a1 : 0.f) - am;
            num = fmaf(oc, acv, num);
        }
        float da2 = (a0 - am) * (a0 - am) + (a1 - am) * (a1 - am) + 6.f * am * am;
        num = wsum(num); do2 = wsum(do2); da2 = wsum(da2);
        corr = num / (sqrtf(do2) * sqrtf(da2) + 1e-8f);
    }

    // ================= GRU (W_hh from smem) =============================
    const float bhr = bhh[j], bhz = bhh[32 + j], bhn = bhh[64 + j];
    const float* gip = g_GI + (size_t)b * NSTEP * NGATE;
    float gr = gip[j], gz = gip[32 + j], gn = gip[64 + j];
    float h = 0.f;
    float* myh = hs[warp];
    const float* wrj = whr[j];
    const float* wzj = whz[j];
    const float* wnj = whn[j];

#pragma unroll 1
    for (int t = 0; t < NSTEP; t++) {
        float ngr = 0.f, ngz = 0.f, ngn = 0.f;
        if (t + 1 < NSTEP) {
            const float* q = gip + (size_t)(t + 1) * NGATE;
            ngr = q[j]; ngz = q[32 + j]; ngn = q[64 + j];
        }
        myh[j] = h;
        __syncwarp();
        float ar0 = 0.f, az0 = 0.f, an0 = 0.f;
        float ar1 = 0.f, az1 = 0.f, an1 = 0.f;
#pragma unroll
        for (int k = 0; k < 16; k++) {
            float h0 = myh[k];
            float h1 = myh[16 + k];
            ar0 = fmaf(wrj[k], h0, ar0);
            az0 = fmaf(wzj[k], h0, az0);
            an0 = fmaf(wnj[k], h0, an0);
            ar1 = fmaf(wrj[16 + k], h1, ar1);
            az1 = fmaf(wzj[16 + k], h1, az1);
            an1 = fmaf(wnj[16 + k], h1, an1);
        }
        float ar = bhr + ar0 + ar1;
        float az = bhz + az0 + az1;
        float an = bhn + an0 + an1;
        float r = sigm(gr + ar);
        float z = sigm(gz + az);
        float n = tanh_fast(gn + r * an);
        __syncwarp();
        h = (1.f - z) * n + z * h;
        gr = ngr; gz = ngz; gn = ngn;
    }

    // ================= layernorm + MLP ==================================
    float* fb = wbuf[warp];
    if (j == 0) { fb[0] = entropy; fb[1] = roc; fb[2] = corr; }
    fb[3 + j] = h;
    __syncwarp();

    float v1 = fb[j];
    float v2 = (j < 3) ? fb[32 + j] : 0.f;
    float mu = wsum(v1 + v2) * (1.f / 35.f);
    float dd1 = v1 - mu;
    float dd2 = (j < 3) ? (v2 - mu) : 0.f;
    float var = wsum(dd1 * dd1 + dd2 * dd2) * (1.f / 35.f);
    float scl = rsqrtf(var + 1e-5f);
    __syncwarp();
    fb[j] = dd1 * scl * gms[j] + bts[j];
    if (j < 3) fb[32 + j] = dd2 * scl * gms[32 + j] + bts[32 + j];
    __syncwarp();

    float* fx1 = fb + 40;
    {
        float acc0 = b1s[j], acc1 = b1s[32 + j];
#pragma unroll
        for (int k = 0; k < 35; k++) {
            float f = fb[k];
            acc0 = fmaf(w1s[j * 35 + k], f, acc0);
            acc1 = fmaf(w1s[(32 + j) * 35 + k], f, acc1);
        }
        fx1[j] = fmaxf(acc0, 0.f);
        fx1[32 + j] = fmaxf(acc1, 0.f);
    }
    __syncwarp();

    float* fx2 = fb + 104;
    {
        float acc = b2s[j];
#pragma unroll
        for (int k = 0; k < 64; k++) acc = fmaf(w2s[j * 65 + k], fx1[k], acc);
        fx2[j] = fmaxf(acc, 0.f);
    }
    __syncwarp();

    float val = -INFINITY;
    if (j < 14) {
        float acc = b3s[j];
#pragma unroll
        for (int k = 0; k < 32; k++) acc = fmaf(w3s[j * 33 + k], fx2[k], acc);
        val = acc;
    }
    int idx = j;
#pragma unroll
    for (int off = 16; off; off >>= 1) {
        float ov = __shfl_down_sync(0xffffffffu, val, off);
        int oi = __shfl_down_sync(0xffffffffu, idx, off);
        if (ov > val || (ov == val && oi < idx)) { val = ov; idx = oi; }
    }
    idx = __shfl_sync(0xffffffffu, idx, 0);

    int wl = idx + 2;
    int s_off = (wl - 1) >> 1;
    int e_off = wl >> 1;

    if (j == 0) out[b] = (float)wl;
    if (j < MAXW) {
        int offp = j - 7;
        float mval = (offp >= -s_off && offp <= e_off) ? 1.f : 0.f;
        out[(size_t)Bn + (size_t)Bn * MAXW * KDIM + (size_t)b * MAXW + j] = mval;
    }

    // ---- padded window: 3 groups of 5 rows ----
    float* pw = out + Bn;
    const float4 z4 = make_float4(0.f, 0.f, 0.f, 0.f);
    const int lo_row = 7 - s_off, hi_row = 7 + e_off;
#pragma unroll
    for (int g = 0; g < 3; g++) {
        float4 va[5], vb[5], vc[5];
#pragma unroll
        for (int r = 0; r < 5; r++) {
            int o = g * 5 + r;
            bool on = (o >= lo_row) && (o <= hi_row);
            if (on) {
                const float4* so = (const float4*)(obs + (size_t)(b * T_TOT + 7 + o) * OBS_DIM);
                va[r] = so[j];
                vb[r] = so[32 + j];
                if (j < 16) {
                    const float4* sa = (const float4*)(act + (size_t)(b * T_TOT + 7 + o) * ACT_DIM);
                    vc[r] = sa[j];
                } else vc[r] = z4;
            } else {
                va[r] = z4; vb[r] = z4; vc[r] = z4;
            }
        }
#pragma unroll
        for (int r = 0; r < 5; r++) {
            int o = g * 5 + r;
            float4* dst = (float4*)(pw + ((size_t)b * MAXW + o) * KDIM);
            dst[j] = va[r];
            dst[32 + j] = vb[r];
            if (j < 16) dst[64 + j] = vc[r];
        }
    }
}

// =====================================================================
extern "C" void kernel_launch(void* const* d_in, const int* in_sizes, int n_in,
                              void* d_out, int out_size)
{
    const float* obs = (const float*)d_in[0];
    const float* act = (const float*)d_in[1];
    const float* Wih = (const float*)d_in[2];
    const float* Whh = (const float*)d_in[3];
    const float* bih = (const float*)d_in[4];
    const float* bhh = (const float*)d_in[5];
    const float* lng = (const float*)d_in[6];
    const float* lnb = (const float*)d_in[7];
    const float* W1  = (const float*)d_in[8];
    const float* b1  = (const float*)d_in[9];
    const float* W2  = (const float*)d_in[10];
    const float* b2  = (const float*)d_in[11];
    const float* W3  = (const float*)d_in[12];
    const float* b3  = (const float*)d_in[13];

    int Bn = in_sizes[0] / (T_TOT * OBS_DIM);
    if (Bn > MAXB) Bn = MAXB;
    float* out = (float*)d_out;

    // one-time setup (first call = correctness run, not captured)
    static bool init_done = false;
    static cudaStream_t s1 = nullptr;
    static cudaEvent_t eg[NCHUNK];
    static cudaEvent_t ef_last = nullptr;
    if (!init_done) {
        cudaFuncSetAttribute(k_gemm_mma, cudaFuncAttributeMaxDynamicSharedMemorySize,
                             GEMM_SMEM_BYTES);
        cudaStreamCreateWithFlags(&s1, cudaStreamNonBlocking);
        for (int c = 0; c < NCHUNK; c++)
            cudaEventCreateWithFlags(&eg[c], cudaEventDisableTiming);
        cudaEventCreateWithFlags(&ef_last, cudaEventDisableTiming);
        init_done = true;
    }

    k_wprep<<<(10 * 4 * NGATE * 4 + 255) / 256, 256>>>(Wih);

    // chunk boundaries (batch elements, multiple of 8)
    int cb[NCHUNK + 1];
    for (int c = 0; c <= NCHUNK; c++)
        cb[c] = (int)((((long long)Bn * c) / NCHUNK) & ~7LL);
    cb[NCHUNK] = Bn;

    // GEMM chunks on the main (capture) stream
    for (int c = 0; c < NCHUNK; c++) {
        int b0 = cb[c], Bc = cb[c + 1] - cb[c];
        if (Bc > 0) {
            int gemm_blocks = (Bc * NSTEP + 127) / 128;
            k_gemm_mma<<<gemm_blocks, 128, GEMM_SMEM_BYTES, 0>>>(obs, act, bih, b0, Bc);
        }
        cudaEventRecord(eg[c], 0);
    }

    // fused chunks on the side stream, gated per-chunk
    for (int c = 0; c < NCHUNK; c++) {
        int b0 = cb[c], Bc = cb[c + 1] - cb[c];
        cudaStreamWaitEvent(s1, eg[c], 0);
        if (Bc <= 0) continue;
        int fused_blocks = (Bc + 7) / 8;
        k_fused<<<fused_blocks, 256, 0, s1>>>(obs, act, Whh, bhh, lng, lnb,
                                              W1, b1, W2, b2, W3, b3,
                                              out, b0, Bc, Bn);
    }

    // join the fork back into the main stream
    cudaEventRecord(ef_last, s1);
    cudaStreamWaitEvent(0, ef_last, 0);
}

// round 14
// speedup vs baseline: 1.0796x; 1.0796x over previous
#include <cuda_runtime.h>
#include <math.h>
#include <stdint.h>

#define OBS_DIM 256
#define ACT_DIM 64
#define T_TOT   22
#define HID     32
#define MAXW    15
#define NSTEP   15
#define NGATE   96
#define KDIM    320
#define MAXB    8192

// GRU pre-activation scratch: GI[(b*15+t)*96 + g]
__device__ float g_GI[(size_t)MAXB * NSTEP * NGATE];
// W_ih fragment-packed: [kt(10)][ks(4)][bn(96)][brow(4)] float4{bh0,bh1,bl0,bl1}
__device__ __align__(16) float4 g_Wp[10 * 4 * NGATE * 4];

__device__ __forceinline__ uint32_t tf32hi_bits(float x) {
    uint32_t h;
    asm("cvt.rna.tf32.f32 %0, %1;" : "=r"(h) : "f"(x));
    return h;
}

__device__ __forceinline__ void mma_tf32(float* c, uint32_t a0, uint32_t a1,
                                         uint32_t a2, uint32_t a3,
                                         uint32_t b0, uint32_t b1) {
    asm volatile(
        "mma.sync.aligned.m16n8k8.row.col.f32.tf32.tf32.f32 "
        "{%0,%1,%2,%3}, {%4,%5,%6,%7}, {%8,%9}, {%0,%1,%2,%3};\n"
        : "+f"(c[0]), "+f"(c[1]), "+f"(c[2]), "+f"(c[3])
        : "r"(a0), "r"(a1), "r"(a2), "r"(a3), "r"(b0), "r"(b1));
}

// ---------- cp.async ----------
__device__ __forceinline__ void cp16(uint32_t dst, const void* src) {
    asm volatile("cp.async.ca.shared.global [%0], [%1], 16;"
                 :: "r"(dst), "l"(src) : "memory");
}
__device__ __forceinline__ void cp_commit() {
    asm volatile("cp.async.commit_group;" ::: "memory");
}
template <int N>
__device__ __forceinline__ void cp_wait() {
    asm volatile("cp.async.wait_group %0;" :: "n"(N) : "memory");
}

__device__ __forceinline__ float wsum(float x) {
#pragma unroll
    for (int o = 16; o; o >>= 1) x += __shfl_xor_sync(0xffffffffu, x, o);
    return x;
}
__device__ __forceinline__ float wmax(float x) {
#pragma unroll
    for (int o = 16; o; o >>= 1) x = fmaxf(x, __shfl_xor_sync(0xffffffffu, x, o));
    return x;
}
__device__ __forceinline__ float sigm(float x) { return 1.f / (1.f + __expf(-x)); }
__device__ __forceinline__ float tanh_fast(float x) {
    float e = __expf(-2.f * fabsf(x));
    float r = (1.f - e) / (1.f + e);
    return copysignf(r, x);
}

// =====================================================================
// Kernel 0: pack W_ih into fragment-ready tf32 hi/lo quads.
// =====================================================================
__global__ void k_wprep(const float* __restrict__ Wih) {
    int p = blockIdx.x * 256 + threadIdx.x;
    if (p >= 10 * 4 * NGATE * 4) return;
    int brow = p & 3;
    int t = p >> 2;
    int bn = t % NGATE;
    int kk8 = t / NGATE;              // 0..39
    int k = kk8 * 8 + brow;
    float x0 = Wih[(size_t)bn * KDIM + k];
    float x1 = Wih[(size_t)bn * KDIM + k + 4];
    float h0 = __uint_as_float(tf32hi_bits(x0));
    float h1 = __uint_as_float(tf32hi_bits(x1));
    g_Wp[p] = make_float4(h0, h1, x0 - h0, x1 - h1);
}

// =====================================================================
// Kernel 1 (R12 known-good ~117us): tensor-core GEMM, cp.async
// double-buffered, monolithic. GI = X @ W^T + b.
// CTA: 128 thr, tile 128m x 96n, warp tile 32m x 96n.
// =====================================================================
#define XSTR 36
#define XTILE (128 * XSTR)                 // floats per X buffer (4608)
#define WTILE (4 * NGATE * 4)              // float4s per W k-tile (1536)
#define GEMM_SMEM_BYTES (2 * XTILE * 4 + 2 * WTILE * 16)   // 86016

__global__ __launch_bounds__(128) void k_gemm_mma(
    const float* __restrict__ obs, const float* __restrict__ act,
    const float* __restrict__ bih, int Bn)
{
    extern __shared__ __align__(16) float4 smem4[];
    float*  Xs = (float*)smem4;                     // [2][128][XSTR] fp32
    float4* Wp = smem4 + (2 * XTILE) / 4;           // [2][4][96][4]
    __shared__ float sbias[96];

    const int tid = threadIdx.x;
    const int warp = tid >> 5, lane = tid & 31;
    const int Mtot = Bn * NSTEP;
    const int m_base = blockIdx.x * 128;

    if (tid < 96) sbias[tid] = bih[tid];

    // per-thread X-load row indices (8 rows, fixed across k-tiles)
    int rowptr[8];
#pragma unroll
    for (int i = 0; i < 8; i++) {
        int idx = i * 128 + tid;
        int r = idx >> 3;
        int gm = m_base + r;
        int gmc = gm < Mtot ? gm : Mtot - 1;
        int bb = gmc / NSTEP;
        int tt = gmc % NSTEP;
        rowptr[i] = bb * T_TOT + tt;
    }
    const int c4 = tid & 7;

    const uint32_t xs_addr = (uint32_t)__cvta_generic_to_shared(Xs);
    const uint32_t wp_addr = (uint32_t)__cvta_generic_to_shared(Wp);

    auto load_tile = [&](int pb, int kt) {
        const int k0 = kt * 32;
        const uint32_t xb = xs_addr + (uint32_t)pb * XTILE * 4;
#pragma unroll
        for (int i = 0; i < 8; i++) {
            int idx = i * 128 + tid;
            int r = idx >> 3;
            int kk = k0 + c4 * 4;
            const float* src = (k0 < OBS_DIM)
                ? obs + (size_t)rowptr[i] * OBS_DIM + kk
                : act + (size_t)rowptr[i] * ACT_DIM + (kk - OBS_DIM);
            cp16(xb + (uint32_t)(r * XSTR + c4 * 4) * 4, src);
        }
        const uint32_t wb = wp_addr + (uint32_t)pb * WTILE * 16;
        const float4* gW = g_Wp + (size_t)kt * WTILE;
#pragma unroll
        for (int i = 0; i < 12; i++) {
            int idx = i * 128 + tid;
            cp16(wb + (uint32_t)idx * 16, gW + idx);
        }
    };

    float acc[2][12][4];
#pragma unroll
    for (int mt = 0; mt < 2; mt++)
#pragma unroll
        for (int nt = 0; nt < 12; nt++)
#pragma unroll
            for (int q = 0; q < 4; q++) acc[mt][nt][q] = 0.f;

    const int ar = lane >> 2, ac = lane & 3;
    const int brow = lane & 3, bcol = lane >> 2;
    const int m0 = warp * 32;

    load_tile(0, 0);
    cp_commit();

#pragma unroll 1
    for (int kt = 0; kt < 10; kt++) {
        const int pb = kt & 1;
        if (kt + 1 < 10) {
            load_tile((kt + 1) & 1, kt + 1);
            cp_commit();
            cp_wait<1>();
        } else {
            cp_wait<0>();
        }
        __syncthreads();

        const float* xp = Xs + pb * XTILE;
        const float4* wp = Wp + pb * WTILE;

#pragma unroll
        for (int ks = 0; ks < 4; ks++) {
            const int kk = ks * 8;
            uint32_t ah[2][4], al[2][4];
#pragma unroll
            for (int mt = 0; mt < 2; mt++) {
                int mr = m0 + mt * 16 + ar;
                float x0 = xp[mr * XSTR + kk + ac];
                float x1 = xp[(mr + 8) * XSTR + kk + ac];
                float x2 = xp[mr * XSTR + kk + ac + 4];
                float x3 = xp[(mr + 8) * XSTR + kk + ac + 4];
                uint32_t h0 = tf32hi_bits(x0);
                uint32_t h1 = tf32hi_bits(x1);
                uint32_t h2 = tf32hi_bits(x2);
                uint32_t h3 = tf32hi_bits(x3);
                ah[mt][0] = h0; al[mt][0] = __float_as_uint(x0 - __uint_as_float(h0));
                ah[mt][1] = h1; al[mt][1] = __float_as_uint(x1 - __uint_as_float(h1));
                ah[mt][2] = h2; al[mt][2] = __float_as_uint(x2 - __uint_as_float(h2));
                ah[mt][3] = h3; al[mt][3] = __float_as_uint(x3 - __uint_as_float(h3));
            }
            const float4* wrow = wp + ks * (NGATE * 4);
#pragma unroll
            for (int nt = 0; nt < 12; nt++) {
                float4 bf = wrow[(nt * 8 + bcol) * 4 + brow];
                uint32_t bh0 = __float_as_uint(bf.x);
                uint32_t bh1 = __float_as_uint(bf.y);
                uint32_t bl0 = __float_as_uint(bf.z);
                uint32_t bl1 = __float_as_uint(bf.w);
#pragma unroll
                for (int mt = 0; mt < 2; mt++) {
                    mma_tf32(acc[mt][nt], ah[mt][0], ah[mt][1], ah[mt][2], ah[mt][3], bh0, bh1);
                    mma_tf32(acc[mt][nt], ah[mt][0], ah[mt][1], ah[mt][2], ah[mt][3], bl0, bl1);
                    mma_tf32(acc[mt][nt], al[mt][0], al[mt][1], al[mt][2], al[mt][3], bh0, bh1);
                }
            }
        }
        __syncthreads();
    }

    // ---- epilogue: C fragments -> GI with bias ----
#pragma unroll
    for (int mt = 0; mt < 2; mt++) {
        const int r0 = m_base + m0 + mt * 16 + (lane >> 2);
        const int r1 = r0 + 8;
#pragma unroll
        for (int nt = 0; nt < 12; nt++) {
            int cc = nt * 8 + 2 * (lane & 3);
            float bx = sbias[cc], by = sbias[cc + 1];
            if (r0 < Mtot) {
                float2 o = make_float2(acc[mt][nt][0] + bx, acc[mt][nt][1] + by);
                *(float2*)(g_GI + (size_t)r0 * NGATE + cc) = o;
            }
            if (r1 < Mtot) {
                float2 o = make_float2(acc[mt][nt][2] + bx, acc[mt][nt][3] + by);
                *(float2*)(g_GI + (size_t)r1 * NGATE + cc) = o;
            }
        }
    }
}

// =====================================================================
// Kernel 2 (fused): now __launch_bounds__(256, 4) for 32 warps/SM.
// =====================================================================
__global__ __launch_bounds__(256, 4) void k_fused(
    const float* __restrict__ obs, const float* __restrict__ act,
    const float* __restrict__ Whh, const float* __restrict__ bhh,
    const float* __restrict__ lng, const float* __restrict__ lnb,
    const float* __restrict__ W1, const float* __restrict__ b1,
    const float* __restrict__ W2, const float* __restrict__ b2,
    const float* __restrict__ W3, const float* __restrict__ b3,
    float* __restrict__ out, int Bn)
{
    __shared__ float whr[32][33], whz[32][33], whn[32][33];
    __shared__ float w1s[64 * 35];
    __shared__ float w2s[32 * 65];
    __shared__ float w3s[14 * 33];
    __shared__ float b1s[64], b2s[32], b3s[14];
    __shared__ float gms[35], bts[35];
    __shared__ float wbuf[8][144];
    __shared__ float hs[8][32];

    const int tid = threadIdx.x;
    for (int i = tid; i < 3 * HID * HID; i += 256) {
        int row = i >> 5, k = i & 31;
        float v = Whh[i];
        if (row < 32)       whr[row][k] = v;
        else if (row < 64)  whz[row - 32][k] = v;
        else                whn[row - 64][k] = v;
    }
    for (int i = tid; i < 64 * 35; i += 256) w1s[i] = W1[i];
    for (int i = tid; i < 32 * 64; i += 256) w2s[(i >> 6) * 65 + (i & 63)] = W2[i];
    for (int i = tid; i < 14 * 32; i += 256) w3s[(i >> 5) * 33 + (i & 31)] = W3[i];
    if (tid < 64) b1s[tid] = b1[tid];
    if (tid < 32) b2s[tid] = b2[tid];
    if (tid < 14) b3s[tid] = b3[tid];
    if (tid < 35) { gms[tid] = lng[tid]; bts[tid] = lnb[tid]; }
    __syncthreads();

    const int warp = tid >> 5, j = tid & 31;
    const int b = blockIdx.x * 8 + warp;
    if (b >= Bn) return;

    // ================= features FIRST ===================================
    float entropy, roc, corr;
    {
        const float* op = obs + (size_t)b * T_TOT * OBS_DIM;
        float o11[8], o12[8], o13[8], o14[8];
#pragma unroll
        for (int i = 0; i < 8; i++) {
            o11[i] = op[11 * OBS_DIM + i * 32 + j];
            o12[i] = op[12 * OBS_DIM + i * 32 + j];
            o13[i] = op[13 * OBS_DIM + i * 32 + j];
            o14[i] = op[14 * OBS_DIM + i * 32 + j];
        }

        float mx = o14[0];
#pragma unroll
        for (int i = 1; i < 8; i++) mx = fmaxf(mx, o14[i]);
        mx = wmax(mx);
        float s = 0.f;
#pragma unroll
        for (int i = 0; i < 8; i++) s += __expf(o14[i] - mx);
        s = wsum(s);
        float inv_s = 1.f / s;
        float es = 0.f;
#pragma unroll
        for (int i = 0; i < 8; i++) {
            float p = __expf(o14[i] - mx) * inv_s;
            es += p * __logf(p + 1e-8f);
        }
        es = wsum(es);
        entropy = -es;

        float d2a = 0.f, d2b = 0.f, d2c = 0.f;
#pragma unroll
        for (int i = 0; i < 8; i++) {
            float da = o12[i] - o11[i]; d2a = fmaf(da, da, d2a);
            float db = o13[i] - o12[i]; d2b = fmaf(db, db, d2b);
            float dc = o14[i] - o13[i]; d2c = fmaf(dc, dc, d2c);
        }
        d2a = wsum(d2a); d2b = wsum(d2b); d2c = wsum(d2c);
        roc = (sqrtf(d2a) + sqrtf(d2b) + sqrtf(d2c)) * (1.f / 3.f);

        float osum = 0.f;
#pragma unroll
        for (int i = 0; i < 8; i++) osum += o14[i];
        osum = wsum(osum);
        float om = osum * (1.f / 256.f);
        const float* ap = act + ((size_t)b * T_TOT + 13) * ACT_DIM;
        float a0 = ap[j], a1 = ap[32 + j];
        float am = wsum(a0 + a1) * (1.f / 256.f);
        float num = 0.f, do2 = 0.f;
#pragma unroll
        for (int i = 0; i < 8; i++) {
            float oc = o14[i] - om;
            do2 = fmaf(oc, oc, do2);
            float acv = ((i == 0) ? a0 : (i == 1) ? a1 : 0.f) - am;
            num = fmaf(oc, acv, num);
        }
        float da2 = (a0 - am) * (a0 - am) + (a1 - am) * (a1 - am) + 6.f * am * am;
        num = wsum(num); do2 = wsum(do2); da2 = wsum(da2);
        corr = num / (sqrtf(do2) * sqrtf(da2) + 1e-8f);
    }

    // ================= GRU (W_hh from smem) =============================
    const float bhr = bhh[j], bhz = bhh[32 + j], bhn = bhh[64 + j];
    const float* gip = g_GI + (size_t)b * NSTEP * NGATE;
    float gr = gip[j], gz = gip[32 + j], gn = gip[64 + j];
    float h = 0.f;
    float* myh = hs[warp];
    const float* wrj = whr[j];
    const float* wzj = whz[j];
    const float* wnj = whn[j];

#pragma unroll 1
    for (int t = 0; t < NSTEP; t++) {
        float ngr = 0.f, ngz = 0.f, ngn = 0.f;
        if (t + 1 < NSTEP) {
            const float* q = gip + (size_t)(t + 1) * NGATE;
            ngr = q[j]; ngz = q[32 + j]; ngn = q[64 + j];
        }
        myh[j] = h;
        __syncwarp();
        float ar0 = 0.f, az0 = 0.f, an0 = 0.f;
        float ar1 = 0.f, az1 = 0.f, an1 = 0.f;
#pragma unroll
        for (int k = 0; k < 16; k++) {
            float h0 = myh[k];
            float h1 = myh[16 + k];
            ar0 = fmaf(wrj[k], h0, ar0);
            az0 = fmaf(wzj[k], h0, az0);
            an0 = fmaf(wnj[k], h0, an0);
            ar1 = fmaf(wrj[16 + k], h1, ar1);
            az1 = fmaf(wzj[16 + k], h1, az1);
            an1 = fmaf(wnj[16 + k], h1, an1);
        }
        float ar = bhr + ar0 + ar1;
        float az = bhz + az0 + az1;
        float an = bhn + an0 + an1;
        float r = sigm(gr + ar);
        float z = sigm(gz + az);
        float n = tanh_fast(gn + r * an);
        __syncwarp();
        h = (1.f - z) * n + z * h;
        gr = ngr; gz = ngz; gn = ngn;
    }

    // ================= layernorm + MLP ==================================
    float* fb = wbuf[warp];
    if (j == 0) { fb[0] = entropy; fb[1] = roc; fb[2] = corr; }
    fb[3 + j] = h;
    __syncwarp();

    float v1 = fb[j];
    float v2 = (j < 3) ? fb[32 + j] : 0.f;
    float mu = wsum(v1 + v2) * (1.f / 35.f);
    float dd1 = v1 - mu;
    float dd2 = (j < 3) ? (v2 - mu) : 0.f;
    float var = wsum(dd1 * dd1 + dd2 * dd2) * (1.f / 35.f);
    float scl = rsqrtf(var + 1e-5f);
    __syncwarp();
    fb[j] = dd1 * scl * gms[j] + bts[j];
    if (j < 3) fb[32 + j] = dd2 * scl * gms[32 + j] + bts[32 + j];
    __syncwarp();

    float* fx1 = fb + 40;
    {
        float acc0 = b1s[j], acc1 = b1s[32 + j];
#pragma unroll
        for (int k = 0; k < 35; k++) {
            float f = fb[k];
            acc0 = fmaf(w1s[j * 35 + k], f, acc0);
            acc1 = fmaf(w1s[(32 + j) * 35 + k], f, acc1);
        }
        fx1[j] = fmaxf(acc0, 0.f);
        fx1[32 + j] = fmaxf(acc1, 0.f);
    }
    __syncwarp();

    float* fx2 = fb + 104;
    {
        float acc = b2s[j];
#pragma unroll
        for (int k = 0; k < 64; k++) acc = fmaf(w2s[j * 65 + k], fx1[k], acc);
        fx2[j] = fmaxf(acc, 0.f);
    }
    __syncwarp();

    float val = -INFINITY;
    if (j < 14) {
        float acc = b3s[j];
#pragma unroll
        for (int k = 0; k < 32; k++) acc = fmaf(w3s[j * 33 + k], fx2[k], acc);
        val = acc;
    }
    int idx = j;
#pragma unroll
    for (int off = 16; off; off >>= 1) {
        float ov = __shfl_down_sync(0xffffffffu, val, off);
        int oi = __shfl_down_sync(0xffffffffu, idx, off);
        if (ov > val || (ov == val && oi < idx)) { val = ov; idx = oi; }
    }
    idx = __shfl_sync(0xffffffffu, idx, 0);

    int wl = idx + 2;
    int s_off = (wl - 1) >> 1;
    int e_off = wl >> 1;

    if (j == 0) out[b] = (float)wl;
    if (j < MAXW) {
        int offp = j - 7;
        float mval = (offp >= -s_off && offp <= e_off) ? 1.f : 0.f;
        out[(size_t)Bn + (size_t)Bn * MAXW * KDIM + (size_t)b * MAXW + j] = mval;
    }

    // ---- padded window: 3 groups of 5 rows ----
    float* pw = out + Bn;
    const float4 z4 = make_float4(0.f, 0.f, 0.f, 0.f);
    const int lo_row = 7 - s_off, hi_row = 7 + e_off;
#pragma unroll
    for (int g = 0; g < 3; g++) {
        float4 va[5], vb[5], vc[5];
#pragma unroll
        for (int r = 0; r < 5; r++) {
            int o = g * 5 + r;
            bool on = (o >= lo_row) && (o <= hi_row);
            if (on) {
                const float4* so = (const float4*)(obs + (size_t)(b * T_TOT + 7 + o) * OBS_DIM);
                va[r] = so[j];
                vb[r] = so[32 + j];
                if (j < 16) {
                    const float4* sa = (const float4*)(act + (size_t)(b * T_TOT + 7 + o) * ACT_DIM);
                    vc[r] = sa[j];
                } else vc[r] = z4;
            } else {
                va[r] = z4; vb[r] = z4; vc[r] = z4;
            }
        }
#pragma unroll
        for (int r = 0; r < 5; r++) {
            int o = g * 5 + r;
            float4* dst = (float4*)(pw + ((size_t)b * MAXW + o) * KDIM);
            dst[j] = va[r];
            dst[32 + j] = vb[r];
            if (j < 16) dst[64 + j] = vc[r];
        }
    }
}

// =====================================================================
extern "C" void kernel_launch(void* const* d_in, const int* in_sizes, int n_in,
                              void* d_out, int out_size)
{
    const float* obs = (const float*)d_in[0];
    const float* act = (const float*)d_in[1];
    const float* Wih = (const float*)d_in[2];
    const float* Whh = (const float*)d_in[3];
    const float* bih = (const float*)d_in[4];
    const float* bhh = (const float*)d_in[5];
    const float* lng = (const float*)d_in[6];
    const float* lnb = (const float*)d_in[7];
    const float* W1  = (const float*)d_in[8];
    const float* b1  = (const float*)d_in[9];
    const float* W2  = (const float*)d_in[10];
    const float* b2  = (const float*)d_in[11];
    const float* W3  = (const float*)d_in[12];
    const float* b3  = (const float*)d_in[13];

    int Bn = in_sizes[0] / (T_TOT * OBS_DIM);
    if (Bn > MAXB) Bn = MAXB;
    float* out = (float*)d_out;

    static bool attr_set = false;
    if (!attr_set) {
        cudaFuncSetAttribute(k_gemm_mma, cudaFuncAttributeMaxDynamicSharedMemorySize,
                             GEMM_SMEM_BYTES);
        attr_set = true;
    }

    k_wprep<<<(10 * 4 * NGATE * 4 + 255) / 256, 256>>>(Wih);

    int Mtot = Bn * NSTEP;
    int gemm_blocks = (Mtot + 127) / 128;
    k_gemm_mma<<<gemm_blocks, 128, GEMM_SMEM_BYTES>>>(obs, act, bih, Bn);

    int fused_blocks = (Bn + 7) / 8;
    k_fused<<<fused_blocks, 256>>>(obs, act, Whh, bhh, lng, lnb,
                                   W1, b1, W2, b2, W3, b3, out, Bn);
}